// round 15
// baseline (speedup 1.0000x reference)
#include <cuda_runtime.h>
#include <cstdint>

// Problem constants
#define BATCH 8
#define CH    96
#define NPIX  3136          // 56*56
#define NODES (BATCH*NPIX)  // 25088
#define KNN   9
#define COUT  192

// dist tiling (R6 proven config + cp.async pipeline)
#define ROWS_B 64           // rows per block
#define CTILE  64           // candidate cols per tile
#define NTILES (NPIX/CTILE) // 49
#define RFS    98           // row-feature smem stride (floats); bank stride 2 -> conflict-free
#define CSS    98           // col-feature smem stride
#define DSS    68           // dist tile stride (multiple of 4 for float4 scan loads)

typedef unsigned long long u64;

__device__ __forceinline__ void ffma2(u64& d, u64 a, u64 b) {
    asm("fma.rn.f32x2 %0, %1, %2, %3;" : "=l"(d) : "l"(a), "l"(b), "l"(d));
}
__device__ __forceinline__ float2 unpack2(u64 a) {
    float2 r; asm("mov.b64 {%0,%1}, %2;" : "=f"(r.x), "=f"(r.y) : "l"(a)); return r;
}
__device__ __forceinline__ u64 pack2(float lo, float hi) {
    u64 r; asm("mov.b64 %0, {%1,%2};" : "=l"(r) : "f"(lo), "f"(hi)); return r;
}
__device__ __forceinline__ uint32_t smem_u32(const void* p) {
    uint32_t a;
    asm("{ .reg .u64 t; cvta.to.shared.u64 t, %1; cvt.u32.u64 %0, t; }" : "=r"(a) : "l"(p));
    return a;
}
__device__ __forceinline__ void cp_async8(uint32_t dst, const void* src) {
    asm volatile("cp.async.ca.shared.global [%0], [%1], 8;" :: "r"(dst), "l"(src));
}
#define CP_COMMIT() asm volatile("cp.async.commit_group;" ::: "memory")
#define CP_WAIT0()  asm volatile("cp.async.wait_group 0;" ::: "memory")

// ---------------- device scratch (static globals; no allocation) ----------------
__device__ float g_xf[NODES*CH];        // [node, c] node features
__device__ float g_sq[NODES];           // per-node squared norm
__device__ int   g_nn[NODES*KNN];       // global neighbor indices, topk order
__device__ int   g_ki[NODES];           // kept degree per node
__device__ float g_W1c[CH*64];          // folded kmap@kfc
__device__ float g_b1c[64];
__device__ float g_W2c[64*KNN];         // folded kmu@kdec
__device__ float g_b2c[KNN];
__device__ float g_Wcat1[192*96];       // [Wa-Wb ; Wb] of ec1
__device__ float g_Wcat2[192*96];       // of ec2
__device__ float g_Wcat3[192*192];      // [io_w@Up1 ; fc_w@Up2]
__device__ float g_bias3[192];
__device__ float g_A1[NODES*192];       // concat feature buffer 1
__device__ float g_A2[NODES*192];       // concat feature buffer 2
__device__ float g_h1[NODES*CH];        // conv1 output

// ---------------- transpose x[B,C,H,W] -> xf[node, c] ----------------
__global__ void transpose_kernel(const float* __restrict__ x) {
    __shared__ float t[32][33];
    int b = blockIdx.z, c0 = blockIdx.y * 32, n0 = blockIdx.x * 32;
    int tx = threadIdx.x, ty = threadIdx.y;
    t[ty][tx] = x[((size_t)b*CH + (c0+ty))*NPIX + (n0+tx)];
    __syncthreads();
    g_xf[((size_t)b*NPIX + (n0+ty))*CH + (c0+tx)] = t[tx][ty];
}

// ---------------- per-node squared norm ----------------
__global__ void sq_kernel() {
    int i = blockIdx.x * blockDim.x + threadIdx.x;
    if (i >= NODES) return;
    const float4* p = (const float4*)(g_xf + (size_t)i*CH);
    float a0=0,a1=0,a2=0,a3=0;
#pragma unroll
    for (int c4 = 0; c4 < CH/4; ++c4) {
        float4 v = p[c4];
        a0 = fmaf(v.x, v.x, a0);
        a1 = fmaf(v.y, v.y, a1);
        a2 = fmaf(v.z, v.z, a2);
        a3 = fmaf(v.w, v.w, a3);
    }
    g_sq[i] = (a0+a1)+(a2+a3);
}

// ---------------- fused weight folding (one launch, k1 k-split x4) ----------------
__global__ __launch_bounds__(256) void mega_prep(
    const float* __restrict__ kmap_w, const float* __restrict__ kmap_b,
    const float* __restrict__ kfc_w,  const float* __restrict__ kfc_b,
    const float* __restrict__ kmu_w,  const float* __restrict__ kmu_b,
    const float* __restrict__ kdec_w, const float* __restrict__ kdec_b,
    const float* __restrict__ ec1_w,  const float* __restrict__ ec2_w,
    const float* __restrict__ io_w,   const float* __restrict__ io_b,
    const float* __restrict__ fc_w,   const float* __restrict__ fc_b,
    const float* __restrict__ up_w,   const float* __restrict__ up_b)
{
    int bid = blockIdx.x;
    if (bid < 97) {
        __shared__ float part[4][64];
        int h = threadIdx.x & 63, s = threadIdx.x >> 6;
        const float* a = (bid < 96) ? (kmap_w + bid*500) : kmap_b;
        float acc = 0.f;
        int k0 = s*125;
        for (int k = k0; k < k0+125; ++k) acc = fmaf(a[k], kfc_w[k*64+h], acc);
        part[s][h] = acc;
        __syncthreads();
        if (s == 0) {
            float v = (part[0][h]+part[1][h]) + (part[2][h]+part[3][h]);
            if (bid < 96) g_W1c[bid*64+h] = v;
            else          g_b1c[h] = v + kfc_b[h];
        }
    } else if (bid < 100) {
        int idx = (bid-97)*256 + threadIdx.x;
        if (idx < 64*KNN) {
            int h = idx / KNN, j = idx % KNN;
            float acc = 0.f;
            for (int t = 0; t < 32; ++t) acc = fmaf(kmu_w[h*32+t], kdec_w[t*KNN+j], acc);
            g_W2c[idx] = acc;
        }
        if (idx < KNN) {
            float acc = kdec_b[idx];
            for (int t = 0; t < 32; ++t) acc = fmaf(kmu_b[t], kdec_w[t*KNN+idx], acc);
            g_b2c[idx] = acc;
        }
    } else if (bid < 172) {
        int idx = (bid-100)*256 + threadIdx.x;
        if (idx < 192*96) {
            int k = idx / 96;
            g_Wcat1[idx] = (k < 96) ? (ec1_w[idx] - ec1_w[idx + 96*96]) : ec1_w[idx];
        }
    } else if (bid < 244) {
        int idx = (bid-172)*256 + threadIdx.x;
        if (idx < 192*96) {
            int k = idx / 96;
            g_Wcat2[idx] = (k < 96) ? (ec2_w[idx] - ec2_w[idx + 96*96]) : ec2_w[idx];
        }
    } else {
        int idx = (bid-244)*256 + threadIdx.x;
        if (idx < 192*192) {
            int r = idx / 192, j = idx % 192;
            float acc = 0.f;
            if (r < 96) {
                for (int t = 0; t < 192; ++t) acc = fmaf(io_w[r*192+t], up_w[t*192+j], acc);
            } else {
                int c = r - 96;
                for (int t = 0; t < 192; ++t) acc = fmaf(fc_w[c*192+t], up_w[(192+t)*192+j], acc);
            }
            g_Wcat3[idx] = acc;
        }
        if (idx < 192) {
            float acc = up_b[idx];
            for (int t = 0; t < 192; ++t) acc = fmaf(io_b[t], up_w[t*192+idx], acc);
            for (int t = 0; t < 192; ++t) acc = fmaf(fc_b[t], up_w[(192+t)*192+idx], acc);
            g_bias3[idx] = acc;
        }
    }
}

// ---------------- GEMM-tiled distance + exact top-9 (cp.async pipelined) ----------------
// R6-proven mainloop: 128 thr, 3 blocks/SM, single wave, 4x8 f32x2 tile, stride-98
// conflict-free LDS.64. New: staging of tile t+1 issued via cp.async AFTER compute t
// releases Cs, landing during scan t (latency hidden); csq double-buffered; 2 barriers
// per tile (was 3). Scan order/semantics identical: 2 strips/row of 32 contiguous cols,
// ascending, strict '<'; in-block lexicographic 2-way merge = exact jax.lax.top_k.
__global__ __launch_bounds__(128, 3) void dist_topk7() {
    extern __shared__ float smem[];
    float* Rf  = smem;                       // [64][RFS]
    float* Cs  = Rf + ROWS_B*RFS;            // [64][CSS]
    float* Ds  = Cs + CTILE*CSS;             // [64][DSS]
    float* csq = Ds + ROWS_B*DSS;            // [2][64]

    int tid = threadIdx.x;
    int b    = blockIdx.y;
    int row0 = blockIdx.x * ROWS_B;
    int grow0 = b * NPIX + row0;
    const float* xb = g_xf + (size_t)b * NPIX * CH;
    uint32_t csAddr = smem_u32(Cs);

    // stage row features [64][96] -> Rf (float2, stride-98 safe)
    for (int idx = tid; idx < ROWS_B*(CH/2); idx += 128) {
        int r = idx / (CH/2), k2 = idx % (CH/2);
        *(float2*)&Rf[r*RFS + k2*2] =
            *(const float2*)(g_xf + (size_t)(grow0 + r)*CH + k2*2);
    }
    // prologue: stage Cs tile 0 + csq[0]
    for (int idx = tid; idx < CTILE*(CH/2); idx += 128) {
        int c = idx / (CH/2), k2 = idx % (CH/2);
        *(float2*)&Cs[c*CSS + k2*2] = *(const float2*)(xb + (size_t)c*CH + k2*2);
    }
    if (tid < CTILE) csq[tid] = g_sq[b*NPIX + tid];
    __syncthreads();

    // mainloop identity: 4 rows x 8 interleaved cols
    int r0 = (tid >> 3) << 2;      // rows r0..r0+3
    int ct = tid & 7;              // cols ct + 8j

    // scan identity: row = tid>>1, strip = tid&1 (contiguous 32 cols)
    int srow = tid >> 1, sstr = tid & 1;
    float rsq = g_sq[grow0 + srow];

    float d[KNN]; int id[KNN];
#pragma unroll
    for (int j = 0; j < KNN; ++j) { d[j] = 3.4e38f; id[j] = 0x7fffffff; }

    for (int tile = 0; tile < NTILES; ++tile) {
        int col0 = tile * CTILE;
        const float* cq = &csq[(tile & 1) * 64];

        // 4x8 outer product over k (f32x2 pairs)
        u64 acc[4][8];
#pragma unroll
        for (int i = 0; i < 4; ++i)
#pragma unroll
            for (int j = 0; j < 8; ++j) acc[i][j] = 0ull;
#pragma unroll 4
        for (int k2 = 0; k2 < CH/2; ++k2) {
            u64 b0 = *(const u64*)&Cs[(ct+ 0)*CSS + 2*k2];
            u64 b1 = *(const u64*)&Cs[(ct+ 8)*CSS + 2*k2];
            u64 b2 = *(const u64*)&Cs[(ct+16)*CSS + 2*k2];
            u64 b3 = *(const u64*)&Cs[(ct+24)*CSS + 2*k2];
            u64 b4 = *(const u64*)&Cs[(ct+32)*CSS + 2*k2];
            u64 b5 = *(const u64*)&Cs[(ct+40)*CSS + 2*k2];
            u64 b6 = *(const u64*)&Cs[(ct+48)*CSS + 2*k2];
            u64 b7 = *(const u64*)&Cs[(ct+56)*CSS + 2*k2];
#pragma unroll
            for (int i = 0; i < 4; ++i) {
                u64 av = *(const u64*)&Rf[(r0+i)*RFS + 2*k2];
                ffma2(acc[i][0], av, b0); ffma2(acc[i][1], av, b1);
                ffma2(acc[i][2], av, b2); ffma2(acc[i][3], av, b3);
                ffma2(acc[i][4], av, b4); ffma2(acc[i][5], av, b5);
                ffma2(acc[i][6], av, b6); ffma2(acc[i][7], av, b7);
            }
        }
#pragma unroll
        for (int i = 0; i < 4; ++i) {
            float* dr = &Ds[(r0+i)*DSS];
#pragma unroll
            for (int j = 0; j < 8; ++j) {
                float2 s = unpack2(acc[i][j]);
                dr[ct + 8*j] = cq[ct + 8*j] - 2.f*(s.x + s.y);
            }
        }
        __syncthreads();   // Ds ready; all warps done reading Cs / csq[tile&1]

        // issue async staging for tile+1 (lands during scan)
        if (tile + 1 < NTILES) {
            int col0n = (tile + 1) * CTILE;
            for (int idx = tid; idx < CTILE*(CH/2); idx += 128) {
                int c = idx / (CH/2), k2 = idx % (CH/2);
                cp_async8(csAddr + (uint32_t)(c*CSS + k2*2)*4u,
                          xb + (size_t)(col0n + c)*CH + k2*2);
            }
            CP_COMMIT();
            if (tid < CTILE) csq[((tile+1) & 1)*64 + tid] = g_sq[b*NPIX + col0n + tid];
        }

        // strip scan: 32 contiguous cols, ascending, strict '<' insert
        {
            const float* dsrow = &Ds[srow*DSS + sstr*32];
            int gbase = b*NPIX + col0 + sstr*32;
#pragma unroll
            for (int t = 0; t < 8; ++t) {
                float4 dv = *(const float4*)&dsrow[t*4];
                float dcs[4] = {rsq + dv.x, rsq + dv.y, rsq + dv.z, rsq + dv.w};
#pragma unroll
                for (int u = 0; u < 4; ++u) {
                    float dc = dcs[u];
                    if (dc < d[KNN-1]) {
                        d[KNN-1] = dc; id[KNN-1] = gbase + t*4 + u;
#pragma unroll
                        for (int j = KNN-1; j > 0; --j) {
                            if (d[j] < d[j-1]) {
                                float td = d[j]; d[j] = d[j-1]; d[j-1] = td;
                                int ti = id[j]; id[j] = id[j-1]; id[j-1] = ti;
                            }
                        }
                    }
                }
            }
        }
        if (tile + 1 < NTILES) CP_WAIT0();
        __syncthreads();   // scan done (Ds free); staged Cs/csq visible to all
    }

    // in-block merge of the 2 strips per row (lexicographic in (d, idx))
    float* pd = Cs;              // reuse smem
    int*   pi = (int*)Rf;
#pragma unroll
    for (int j = 0; j < KNN; ++j) { pd[tid*KNN + j] = d[j]; pi[tid*KNN + j] = id[j]; }
    __syncthreads();
    if (sstr == 0) {
        const float* dA = &pd[tid*KNN];      const int* iA = &pi[tid*KNN];
        const float* dB = &pd[(tid+1)*KNN];  const int* iB = &pi[(tid+1)*KNN];
        int p = 0, q = 0;
        int* dst = g_nn + (size_t)(grow0 + srow)*KNN;
#pragma unroll
        for (int j = 0; j < KNN; ++j) {
            float da = dA[p], db = dB[q];
            bool takeA = (da < db) || (da == db && iA[p] < iB[q]);
            dst[j] = takeA ? iA[p++] : iB[q++];
        }
    }
}

// ---------------- folded K-predictor MLP + argmax (float4 weights, h-accums) ----------------
__global__ __launch_bounds__(128) void kmlp_kernel() {
    __shared__ __align__(16) float sW1[CH*64];
    __shared__ float sW2[64*KNN];
    __shared__ float sb1[64];
    __shared__ float sb2[KNN];
    for (int t = threadIdx.x; t < CH*64; t += 128) sW1[t] = g_W1c[t];
    for (int t = threadIdx.x; t < 64*KNN; t += 128) sW2[t] = g_W2c[t];
    if (threadIdx.x < 64) sb1[threadIdx.x] = g_b1c[threadIdx.x];
    if (threadIdx.x < KNN) sb2[threadIdx.x] = g_b2c[threadIdx.x];
    __syncthreads();

    int i = blockIdx.x * 128 + threadIdx.x;
    float xr[CH];
#pragma unroll
    for (int c4 = 0; c4 < CH/4; ++c4) {
        float4 v = *(const float4*)(g_xf + (size_t)i*CH + c4*4);
        xr[c4*4+0]=v.x; xr[c4*4+1]=v.y; xr[c4*4+2]=v.z; xr[c4*4+3]=v.w;
    }
    float lg[KNN];
#pragma unroll
    for (int j = 0; j < KNN; ++j) lg[j] = sb2[j];

#pragma unroll
    for (int half = 0; half < 2; ++half) {
        float hacc[32];
#pragma unroll
        for (int h = 0; h < 32; ++h) hacc[h] = sb1[half*32 + h];
        for (int c = 0; c < CH; ++c) {
            float xc = xr[c];
            const float4* w4 = (const float4*)&sW1[c*64 + half*32];
#pragma unroll
            for (int q = 0; q < 8; ++q) {
                float4 w = w4[q];
                hacc[q*4+0] = fmaf(xc, w.x, hacc[q*4+0]);
                hacc[q*4+1] = fmaf(xc, w.y, hacc[q*4+1]);
                hacc[q*4+2] = fmaf(xc, w.z, hacc[q*4+2]);
                hacc[q*4+3] = fmaf(xc, w.w, hacc[q*4+3]);
            }
        }
#pragma unroll
        for (int h = 0; h < 32; ++h) {
            float hv = fmaxf(hacc[h], 0.f);
            int hh = half*32 + h;
#pragma unroll
            for (int j = 0; j < KNN; ++j) lg[j] = fmaf(hv, sW2[hh*KNN+j], lg[j]);
        }
    }
    float best = lg[0]; int bi = 0;
#pragma unroll
    for (int j = 1; j < KNN; ++j) if (lg[j] > best) { best = lg[j]; bi = j; }
    g_ki[i] = bi;
}

// ---------------- gather: A = [ki*feat_i | sum_{k<ki} feat_{nn[k]}] ----------------
// mode 1 also drops xf into A1[:,0:96] for the final concat.
__global__ void gather_kernel(int mode) {
    const float* feat = mode ? g_h1 : g_xf;
    float*       A    = mode ? g_A2 : g_A1;
    int idx = blockIdx.x * blockDim.x + threadIdx.x;
    if (idx >= NODES*CH) return;
    int i = idx / CH, c = idx % CH;
    int k = g_ki[i];
    const int* nrow = g_nn + (size_t)i*KNN;
    float s = 0.f;
    for (int e = 0; e < k; ++e) s += feat[(size_t)nrow[e]*CH + c];
    A[(size_t)i*192 + c]      = (float)k * feat[(size_t)i*CH + c];
    A[(size_t)i*192 + 96 + c] = s;
    if (mode) g_A1[(size_t)i*192 + c] = g_xf[(size_t)i*CH + c];
}

// ---------------- GEMM [25088,192] @ [192, 96-col tile], f32x2-packed ----------------
__global__ __launch_bounds__(256) void gemm_kernel(int mode, const float* __restrict__ bias_in,
                                                   float* __restrict__ dout) {
    const float* A; const float* W; const float* bias; float* C;
    int ldw, ldc, relu, usek, trans;
    if (mode == 0)      { A=g_A1; W=g_Wcat1; bias=bias_in; C=g_h1;    ldw=96;  ldc=96;  relu=1; usek=1; trans=0; }
    else if (mode == 1) { A=g_A2; W=g_Wcat2; bias=bias_in; C=g_A1+96; ldw=96;  ldc=192; relu=0; usek=1; trans=0; }
    else                { A=g_A1; W=g_Wcat3; bias=g_bias3; C=dout;    ldw=192; ldc=192; relu=1; usek=0; trans=1; }

    __shared__ float As[16][128];
    __shared__ float Bs[16][96];
    int tid = threadIdx.x;
    int tx = tid % 16, ty = tid / 16;
    int row0 = blockIdx.x * 128;
    int col0 = blockIdx.y * 96;

    u64 acc2[4][6];
#pragma unroll
    for (int p = 0; p < 4; ++p)
#pragma unroll
        for (int j = 0; j < 6; ++j) acc2[p][j] = 0ull;

    for (int kk = 0; kk < 192; kk += 16) {
#pragma unroll
        for (int l = 0; l < 2; ++l) {
            int idx = tid + l*256;
            int r = idx >> 2, k4 = idx & 3;
            float4 v = *(const float4*)(A + (size_t)(row0 + r)*192 + kk + k4*4);
            As[k4*4+0][r] = v.x; As[k4*4+1][r] = v.y; As[k4*4+2][r] = v.z; As[k4*4+3][r] = v.w;
        }
#pragma unroll
        for (int l = 0; l < 2; ++l) {
            int idx = tid + l*256;
            if (idx < 384) {
                int k = idx / 24, c4 = idx % 24;
                float4 v = *(const float4*)(W + (size_t)(kk+k)*ldw + col0 + c4*4);
                *(float4*)&Bs[k][c4*4] = v;
            }
        }
        __syncthreads();
#pragma unroll
        for (int k = 0; k < 16; ++k) {
            ulonglong2 a01 = *(const ulonglong2*)&As[k][ty*8];
            ulonglong2 a23 = *(const ulonglong2*)&As[k][ty*8+4];
            u64 ap[4] = {a01.x, a01.y, a23.x, a23.y};
            float2 bv0 = *(const float2*)&Bs[k][tx*6];
            float2 bv1 = *(const float2*)&Bs[k][tx*6+2];
            float2 bv2 = *(const float2*)&Bs[k][tx*6+4];
            u64 bp[6];
            bp[0] = pack2(bv0.x, bv0.x); bp[1] = pack2(bv0.y, bv0.y);
            bp[2] = pack2(bv1.x, bv1.x); bp[3] = pack2(bv1.y, bv1.y);
            bp[4] = pack2(bv2.x, bv2.x); bp[5] = pack2(bv2.y, bv2.y);
#pragma unroll
            for (int p = 0; p < 4; ++p)
#pragma unroll
                for (int j = 0; j < 6; ++j) ffma2(acc2[p][j], ap[p], bp[j]);
        }
        __syncthreads();
    }

#pragma unroll
    for (int p = 0; p < 4; ++p) {
        int rlo = row0 + ty*8 + 2*p;
        float klo = usek ? (float)g_ki[rlo]   : 1.f;
        float khi = usek ? (float)g_ki[rlo+1] : 1.f;
#pragma unroll
        for (int j = 0; j < 6; ++j) {
            int col = col0 + tx*6 + j;
            float2 v2 = unpack2(acc2[p][j]);
            float vlo = v2.x + bias[col] * klo;
            float vhi = v2.y + bias[col] * khi;
            if (relu) { vlo = fmaxf(vlo, 0.f); vhi = fmaxf(vhi, 0.f); }
            if (trans) {
                int blo = rlo / NPIX, nlo = rlo % NPIX;
                int bhi = (rlo+1) / NPIX, nhi = (rlo+1) % NPIX;
                C[((size_t)(blo*192 + col))*NPIX + nlo] = vlo;
                C[((size_t)(bhi*192 + col))*NPIX + nhi] = vhi;
            } else {
                C[(size_t)rlo*ldc + col]     = vlo;
                C[(size_t)(rlo+1)*ldc + col] = vhi;
            }
        }
    }
}

// ---------------- launch ----------------
extern "C" void kernel_launch(void* const* d_in, const int* in_sizes, int n_in,
                              void* d_out, int out_size) {
    const float* x      = (const float*)d_in[0];
    const float* kmap_w = (const float*)d_in[1];
    const float* kmap_b = (const float*)d_in[2];
    const float* kfc_w  = (const float*)d_in[3];
    const float* kfc_b  = (const float*)d_in[4];
    const float* kmu_w  = (const float*)d_in[5];
    const float* kmu_b  = (const float*)d_in[6];
    const float* kdec_w = (const float*)d_in[7];
    const float* kdec_b = (const float*)d_in[8];
    const float* ec1_w  = (const float*)d_in[9];
    const float* ec1_b  = (const float*)d_in[10];
    const float* ec2_w  = (const float*)d_in[11];
    const float* ec2_b  = (const float*)d_in[12];
    const float* fc_w   = (const float*)d_in[13];
    const float* fc_b   = (const float*)d_in[14];
    const float* io_w   = (const float*)d_in[15];
    const float* io_b   = (const float*)d_in[16];
    const float* up_w   = (const float*)d_in[17];
    const float* up_b   = (const float*)d_in[18];
    float* out = (float*)d_out;

    const int dist_smem = (ROWS_B*RFS + CTILE*CSS + ROWS_B*DSS + 2*CTILE) * 4;  // 68096
    cudaFuncSetAttribute(dist_topk7, cudaFuncAttributeMaxDynamicSharedMemorySize, dist_smem);

    transpose_kernel<<<dim3(NPIX/32, CH/32, BATCH), dim3(32,32)>>>(x);
    sq_kernel<<<(NODES+255)/256, 256>>>();
    mega_prep<<<388, 256>>>(kmap_w, kmap_b, kfc_w, kfc_b, kmu_w, kmu_b,
                            kdec_w, kdec_b, ec1_w, ec2_w,
                            io_w, io_b, fc_w, fc_b, up_w, up_b);

    dist_topk7<<<dim3(NPIX/ROWS_B, BATCH), 128, dist_smem>>>();
    kmlp_kernel<<<NODES/128, 128>>>();

    gather_kernel<<<(NODES*CH+255)/256, 256>>>(0);
    gemm_kernel<<<dim3(NODES/128, 1), 256>>>(0, ec1_b, nullptr);
    gather_kernel<<<(NODES*CH+255)/256, 256>>>(1);
    gemm_kernel<<<dim3(NODES/128, 1), 256>>>(1, ec2_b, nullptr);
    gemm_kernel<<<dim3(NODES/128, 2), 256>>>(2, nullptr, out);
    (void)in_sizes; (void)n_in; (void)out_size;
}

// round 16
// speedup vs baseline: 1.6155x; 1.6155x over previous
#include <cuda_runtime.h>
#include <cstdint>

// Problem constants
#define BATCH 8
#define CH    96
#define NPIX  3136          // 56*56
#define NODES (BATCH*NPIX)  // 25088
#define KNN   9
#define COUT  192

// dist tiling (R6/R14 proven config -- DO NOT TOUCH)
#define ROWS_B 64           // rows per block
#define CTILE  64           // candidate cols per tile
#define NTILES (NPIX/CTILE) // 49
#define RFS    98           // row-feature smem stride (floats); bank stride 2 -> conflict-free
#define CSS    98           // col-feature smem stride
#define DSS    68           // dist tile stride (multiple of 4 for float4 scan loads)

typedef unsigned long long u64;

__device__ __forceinline__ void ffma2(u64& d, u64 a, u64 b) {
    asm("fma.rn.f32x2 %0, %1, %2, %3;" : "=l"(d) : "l"(a), "l"(b), "l"(d));
}
__device__ __forceinline__ float2 unpack2(u64 a) {
    float2 r; asm("mov.b64 {%0,%1}, %2;" : "=f"(r.x), "=f"(r.y) : "l"(a)); return r;
}
__device__ __forceinline__ u64 pack2(float lo, float hi) {
    u64 r; asm("mov.b64 %0, {%1,%2};" : "=l"(r) : "f"(lo), "f"(hi)); return r;
}

// ---------------- device scratch (static globals; no allocation) ----------------
__device__ float g_xf[NODES*CH];        // [node, c] node features
__device__ float g_sq[NODES];           // per-node squared norm
__device__ int   g_nn[NODES*KNN];       // global neighbor indices, topk order
__device__ int   g_ki[NODES];           // kept degree per node
__device__ float g_W1c[CH*64];          // folded kmap@kfc
__device__ float g_b1c[64];
__device__ float g_W2c[64*KNN];         // folded kmu@kdec
__device__ float g_b2c[KNN];
__device__ float g_Wcat1[192*96];       // [Wa-Wb ; Wb] of ec1
__device__ float g_Wcat2[192*96];       // of ec2
__device__ float g_Wcat3[192*192];      // [io_w@Up1 ; fc_w@Up2]
__device__ float g_bias3[192];
__device__ float g_A1[NODES*192];       // concat feature buffer 1
__device__ float g_A2[NODES*192];       // concat feature buffer 2
__device__ float g_h1[NODES*CH];        // conv1 output

// ---------------- transpose x[B,C,H,W] -> xf[node, c] ----------------
__global__ void transpose_kernel(const float* __restrict__ x) {
    __shared__ float t[32][33];
    int b = blockIdx.z, c0 = blockIdx.y * 32, n0 = blockIdx.x * 32;
    int tx = threadIdx.x, ty = threadIdx.y;
    t[ty][tx] = x[((size_t)b*CH + (c0+ty))*NPIX + (n0+tx)];
    __syncthreads();
    g_xf[((size_t)b*NPIX + (n0+ty))*CH + (c0+tx)] = t[tx][ty];
}

// ---------------- per-node squared norm ----------------
__global__ void sq_kernel() {
    int i = blockIdx.x * blockDim.x + threadIdx.x;
    if (i >= NODES) return;
    const float4* p = (const float4*)(g_xf + (size_t)i*CH);
    float a0=0,a1=0,a2=0,a3=0;
#pragma unroll
    for (int c4 = 0; c4 < CH/4; ++c4) {
        float4 v = p[c4];
        a0 = fmaf(v.x, v.x, a0);
        a1 = fmaf(v.y, v.y, a1);
        a2 = fmaf(v.z, v.z, a2);
        a3 = fmaf(v.w, v.w, a3);
    }
    g_sq[i] = (a0+a1)+(a2+a3);
}

// ---------------- fused weight folding (one launch, k1 k-split x4; R10 proven) ----------------
__global__ __launch_bounds__(256) void mega_prep(
    const float* __restrict__ kmap_w, const float* __restrict__ kmap_b,
    const float* __restrict__ kfc_w,  const float* __restrict__ kfc_b,
    const float* __restrict__ kmu_w,  const float* __restrict__ kmu_b,
    const float* __restrict__ kdec_w, const float* __restrict__ kdec_b,
    const float* __restrict__ ec1_w,  const float* __restrict__ ec2_w,
    const float* __restrict__ io_w,   const float* __restrict__ io_b,
    const float* __restrict__ fc_w,   const float* __restrict__ fc_b,
    const float* __restrict__ up_w,   const float* __restrict__ up_b)
{
    int bid = blockIdx.x;
    if (bid < 97) {
        __shared__ float part[4][64];
        int h = threadIdx.x & 63, s = threadIdx.x >> 6;
        const float* a = (bid < 96) ? (kmap_w + bid*500) : kmap_b;
        float acc = 0.f;
        int k0 = s*125;
        for (int k = k0; k < k0+125; ++k) acc = fmaf(a[k], kfc_w[k*64+h], acc);
        part[s][h] = acc;
        __syncthreads();
        if (s == 0) {
            float v = (part[0][h]+part[1][h]) + (part[2][h]+part[3][h]);
            if (bid < 96) g_W1c[bid*64+h] = v;
            else          g_b1c[h] = v + kfc_b[h];
        }
    } else if (bid < 100) {
        int idx = (bid-97)*256 + threadIdx.x;
        if (idx < 64*KNN) {
            int h = idx / KNN, j = idx % KNN;
            float acc = 0.f;
            for (int t = 0; t < 32; ++t) acc = fmaf(kmu_w[h*32+t], kdec_w[t*KNN+j], acc);
            g_W2c[idx] = acc;
        }
        if (idx < KNN) {
            float acc = kdec_b[idx];
            for (int t = 0; t < 32; ++t) acc = fmaf(kmu_b[t], kdec_w[t*KNN+idx], acc);
            g_b2c[idx] = acc;
        }
    } else if (bid < 172) {
        int idx = (bid-100)*256 + threadIdx.x;
        if (idx < 192*96) {
            int k = idx / 96;
            g_Wcat1[idx] = (k < 96) ? (ec1_w[idx] - ec1_w[idx + 96*96]) : ec1_w[idx];
        }
    } else if (bid < 244) {
        int idx = (bid-172)*256 + threadIdx.x;
        if (idx < 192*96) {
            int k = idx / 96;
            g_Wcat2[idx] = (k < 96) ? (ec2_w[idx] - ec2_w[idx + 96*96]) : ec2_w[idx];
        }
    } else {
        int idx = (bid-244)*256 + threadIdx.x;
        if (idx < 192*192) {
            int r = idx / 192, j = idx % 192;
            float acc = 0.f;
            if (r < 96) {
                for (int t = 0; t < 192; ++t) acc = fmaf(io_w[r*192+t], up_w[t*192+j], acc);
            } else {
                int c = r - 96;
                for (int t = 0; t < 192; ++t) acc = fmaf(fc_w[c*192+t], up_w[(192+t)*192+j], acc);
            }
            g_Wcat3[idx] = acc;
        }
        if (idx < 192) {
            float acc = up_b[idx];
            for (int t = 0; t < 192; ++t) acc = fmaf(io_b[t], up_w[t*192+idx], acc);
            for (int t = 0; t < 192; ++t) acc = fmaf(fc_b[t], up_w[(192+t)*192+idx], acc);
            g_bias3[idx] = acc;
        }
    }
}

// ---------------- GEMM-tiled distance + exact top-9 (R6/R14 proven, verbatim) ----------------
// 128 threads/block, 3 blocks/SM, single wave (392 blocks). Block: 64 rows x all
// 49 tiles of 64 cols. Thread tile 4 rows x 8 interleaved cols {ct+8j}: per k-pair
// 12 one-phase LDS.64 feed 32 FFMA2. Scan: 2 strips/row of 32 contiguous cols,
// ascending, strict '<'; in-block lexicographic 2-way merge reproduces exact
// jax.lax.top_k tie semantics.
__global__ __launch_bounds__(128, 3) void dist_topk5() {
    extern __shared__ float smem[];
    float* Rf  = smem;                       // [64][RFS]
    float* Cs  = Rf + ROWS_B*RFS;            // [64][CSS]
    float* Ds  = Cs + CTILE*CSS;             // [64][DSS]
    float* csq = Ds + ROWS_B*DSS;            // [64]

    int tid = threadIdx.x;
    int b    = blockIdx.y;
    int row0 = blockIdx.x * ROWS_B;
    int grow0 = b * NPIX + row0;
    const float* xb = g_xf + (size_t)b * NPIX * CH;

    // stage row features [64][96] -> Rf (float2, stride-98 safe)
    for (int idx = tid; idx < ROWS_B*(CH/2); idx += 128) {
        int r = idx / (CH/2), k2 = idx % (CH/2);
        *(float2*)&Rf[r*RFS + k2*2] =
            *(const float2*)(g_xf + (size_t)(grow0 + r)*CH + k2*2);
    }

    // mainloop identity: 4 rows x 8 interleaved cols
    int r0 = (tid >> 3) << 2;      // rows r0..r0+3
    int ct = tid & 7;              // cols ct + 8j

    // scan identity: row = tid>>1, strip = tid&1 (contiguous 32 cols)
    int srow = tid >> 1, sstr = tid & 1;
    float rsq = g_sq[grow0 + srow];

    float d[KNN]; int id[KNN];
#pragma unroll
    for (int j = 0; j < KNN; ++j) { d[j] = 3.4e38f; id[j] = 0x7fffffff; }

    for (int tile = 0; tile < NTILES; ++tile) {
        int col0 = tile * CTILE;
        // stage candidate features [64][96] -> Cs, plus csq
        for (int idx = tid; idx < CTILE*(CH/2); idx += 128) {
            int c = idx / (CH/2), k2 = idx % (CH/2);
            *(float2*)&Cs[c*CSS + k2*2] =
                *(const float2*)(xb + (size_t)(col0 + c)*CH + k2*2);
        }
        if (tid < CTILE) csq[tid] = g_sq[b*NPIX + col0 + tid];
        __syncthreads();

        // 4x8 outer product over k (f32x2 pairs)
        u64 acc[4][8];
#pragma unroll
        for (int i = 0; i < 4; ++i)
#pragma unroll
            for (int j = 0; j < 8; ++j) acc[i][j] = 0ull;
#pragma unroll 4
        for (int k2 = 0; k2 < CH/2; ++k2) {
            u64 b0 = *(const u64*)&Cs[(ct+ 0)*CSS + 2*k2];
            u64 b1 = *(const u64*)&Cs[(ct+ 8)*CSS + 2*k2];
            u64 b2 = *(const u64*)&Cs[(ct+16)*CSS + 2*k2];
            u64 b3 = *(const u64*)&Cs[(ct+24)*CSS + 2*k2];
            u64 b4 = *(const u64*)&Cs[(ct+32)*CSS + 2*k2];
            u64 b5 = *(const u64*)&Cs[(ct+40)*CSS + 2*k2];
            u64 b6 = *(const u64*)&Cs[(ct+48)*CSS + 2*k2];
            u64 b7 = *(const u64*)&Cs[(ct+56)*CSS + 2*k2];
#pragma unroll
            for (int i = 0; i < 4; ++i) {
                u64 av = *(const u64*)&Rf[(r0+i)*RFS + 2*k2];
                ffma2(acc[i][0], av, b0); ffma2(acc[i][1], av, b1);
                ffma2(acc[i][2], av, b2); ffma2(acc[i][3], av, b3);
                ffma2(acc[i][4], av, b4); ffma2(acc[i][5], av, b5);
                ffma2(acc[i][6], av, b6); ffma2(acc[i][7], av, b7);
            }
        }
#pragma unroll
        for (int i = 0; i < 4; ++i) {
            float* dr = &Ds[(r0+i)*DSS];
#pragma unroll
            for (int j = 0; j < 8; ++j) {
                float2 s = unpack2(acc[i][j]);
                dr[ct + 8*j] = csq[ct + 8*j] - 2.f*(s.x + s.y);
            }
        }
        __syncthreads();

        // strip scan: 32 contiguous cols, ascending, strict '<' insert
        const float* dsrow = &Ds[srow*DSS + sstr*32];
        int gbase = b*NPIX + col0 + sstr*32;
#pragma unroll
        for (int t = 0; t < 8; ++t) {
            float4 dv = *(const float4*)&dsrow[t*4];
            float dcs[4] = {rsq + dv.x, rsq + dv.y, rsq + dv.z, rsq + dv.w};
#pragma unroll
            for (int u = 0; u < 4; ++u) {
                float dc = dcs[u];
                if (dc < d[KNN-1]) {
                    d[KNN-1] = dc; id[KNN-1] = gbase + t*4 + u;
#pragma unroll
                    for (int j = KNN-1; j > 0; --j) {
                        if (d[j] < d[j-1]) {
                            float td = d[j]; d[j] = d[j-1]; d[j-1] = td;
                            int ti = id[j]; id[j] = id[j-1]; id[j-1] = ti;
                        }
                    }
                }
            }
        }
        __syncthreads();   // scans done before next tile restages Cs / rewrites Ds
    }

    // in-block merge of the 2 strips per row (lexicographic in (d, idx))
    float* pd = Cs;              // reuse smem
    int*   pi = (int*)Rf;
#pragma unroll
    for (int j = 0; j < KNN; ++j) { pd[tid*KNN + j] = d[j]; pi[tid*KNN + j] = id[j]; }
    __syncthreads();
    if (sstr == 0) {
        const float* dA = &pd[tid*KNN];      const int* iA = &pi[tid*KNN];
        const float* dB = &pd[(tid+1)*KNN];  const int* iB = &pi[(tid+1)*KNN];
        int p = 0, q = 0;
        int* dst = g_nn + (size_t)(grow0 + srow)*KNN;
#pragma unroll
        for (int j = 0; j < KNN; ++j) {
            float da = dA[p], db = dB[q];
            bool takeA = (da < db) || (da == db && iA[p] < iB[q]);
            dst[j] = takeA ? iA[p++] : iB[q++];
        }
    }
}

// ---------------- folded K-predictor MLP + argmax (R14 proven form) ----------------
__global__ __launch_bounds__(128) void kmlp_kernel() {
    __shared__ float sW1[CH*64];
    __shared__ float sW2[64*KNN];
    __shared__ float sb1[64];
    __shared__ float sb2[KNN];
    for (int t = threadIdx.x; t < CH*64; t += 128) sW1[t] = g_W1c[t];
    for (int t = threadIdx.x; t < 64*KNN; t += 128) sW2[t] = g_W2c[t];
    if (threadIdx.x < 64) sb1[threadIdx.x] = g_b1c[threadIdx.x];
    if (threadIdx.x < KNN) sb2[threadIdx.x] = g_b2c[threadIdx.x];
    __syncthreads();

    int i = blockIdx.x * 128 + threadIdx.x;
    float xr[CH];
#pragma unroll
    for (int c4 = 0; c4 < CH/4; ++c4) {
        float4 v = *(const float4*)(g_xf + (size_t)i*CH + c4*4);
        xr[c4*4+0]=v.x; xr[c4*4+1]=v.y; xr[c4*4+2]=v.z; xr[c4*4+3]=v.w;
    }
    float lg[KNN];
#pragma unroll
    for (int j = 0; j < KNN; ++j) lg[j] = sb2[j];

    for (int h = 0; h < 64; ++h) {
        float a0=0,a1=0,a2=0,a3=0;
#pragma unroll
        for (int c = 0; c < CH; c += 4) {
            a0 = fmaf(xr[c+0], sW1[(c+0)*64+h], a0);
            a1 = fmaf(xr[c+1], sW1[(c+1)*64+h], a1);
            a2 = fmaf(xr[c+2], sW1[(c+2)*64+h], a2);
            a3 = fmaf(xr[c+3], sW1[(c+3)*64+h], a3);
        }
        float hv = fmaxf((a0+a1)+(a2+a3) + sb1[h], 0.f);
#pragma unroll
        for (int j = 0; j < KNN; ++j) lg[j] = fmaf(hv, sW2[h*KNN+j], lg[j]);
    }
    float best = lg[0]; int bi = 0;
#pragma unroll
    for (int j = 1; j < KNN; ++j) if (lg[j] > best) { best = lg[j]; bi = j; }
    g_ki[i] = bi;
}

// ---------------- gather: A = [ki*feat_i | sum_{k<ki} feat_{nn[k]}] ----------------
// mode 1 also drops xf into A1[:,0:96] for the final concat.
__global__ void gather_kernel(int mode) {
    const float* feat = mode ? g_h1 : g_xf;
    float*       A    = mode ? g_A2 : g_A1;
    int idx = blockIdx.x * blockDim.x + threadIdx.x;
    if (idx >= NODES*CH) return;
    int i = idx / CH, c = idx % CH;
    int k = g_ki[i];
    const int* nrow = g_nn + (size_t)i*KNN;
    float s = 0.f;
    for (int e = 0; e < k; ++e) s += feat[(size_t)nrow[e]*CH + c];
    A[(size_t)i*192 + c]      = (float)k * feat[(size_t)i*CH + c];
    A[(size_t)i*192 + 96 + c] = s;
    if (mode) g_A1[(size_t)i*192 + c] = g_xf[(size_t)i*CH + c];
}

// ---------------- GEMM [25088,192] @ [192, 96-col tile], f32x2-packed ----------------
__global__ __launch_bounds__(256) void gemm_kernel(int mode, const float* __restrict__ bias_in,
                                                   float* __restrict__ dout) {
    const float* A; const float* W; const float* bias; float* C;
    int ldw, ldc, relu, usek, trans;
    if (mode == 0)      { A=g_A1; W=g_Wcat1; bias=bias_in; C=g_h1;    ldw=96;  ldc=96;  relu=1; usek=1; trans=0; }
    else if (mode == 1) { A=g_A2; W=g_Wcat2; bias=bias_in; C=g_A1+96; ldw=96;  ldc=192; relu=0; usek=1; trans=0; }
    else                { A=g_A1; W=g_Wcat3; bias=g_bias3; C=dout;    ldw=192; ldc=192; relu=1; usek=0; trans=1; }

    __shared__ float As[16][128];
    __shared__ float Bs[16][96];
    int tid = threadIdx.x;
    int tx = tid % 16, ty = tid / 16;
    int row0 = blockIdx.x * 128;
    int col0 = blockIdx.y * 96;

    u64 acc2[4][6];
#pragma unroll
    for (int p = 0; p < 4; ++p)
#pragma unroll
        for (int j = 0; j < 6; ++j) acc2[p][j] = 0ull;

    for (int kk = 0; kk < 192; kk += 16) {
#pragma unroll
        for (int l = 0; l < 2; ++l) {
            int idx = tid + l*256;
            int r = idx >> 2, k4 = idx & 3;
            float4 v = *(const float4*)(A + (size_t)(row0 + r)*192 + kk + k4*4);
            As[k4*4+0][r] = v.x; As[k4*4+1][r] = v.y; As[k4*4+2][r] = v.z; As[k4*4+3][r] = v.w;
        }
#pragma unroll
        for (int l = 0; l < 2; ++l) {
            int idx = tid + l*256;
            if (idx < 384) {
                int k = idx / 24, c4 = idx % 24;
                float4 v = *(const float4*)(W + (size_t)(kk+k)*ldw + col0 + c4*4);
                *(float4*)&Bs[k][c4*4] = v;
            }
        }
        __syncthreads();
#pragma unroll
        for (int k = 0; k < 16; ++k) {
            ulonglong2 a01 = *(const ulonglong2*)&As[k][ty*8];
            ulonglong2 a23 = *(const ulonglong2*)&As[k][ty*8+4];
            u64 ap[4] = {a01.x, a01.y, a23.x, a23.y};
            float2 bv0 = *(const float2*)&Bs[k][tx*6];
            float2 bv1 = *(const float2*)&Bs[k][tx*6+2];
            float2 bv2 = *(const float2*)&Bs[k][tx*6+4];
            u64 bp[6];
            bp[0] = pack2(bv0.x, bv0.x); bp[1] = pack2(bv0.y, bv0.y);
            bp[2] = pack2(bv1.x, bv1.x); bp[3] = pack2(bv1.y, bv1.y);
            bp[4] = pack2(bv2.x, bv2.x); bp[5] = pack2(bv2.y, bv2.y);
#pragma unroll
            for (int p = 0; p < 4; ++p)
#pragma unroll
                for (int j = 0; j < 6; ++j) ffma2(acc2[p][j], ap[p], bp[j]);
        }
        __syncthreads();
    }

#pragma unroll
    for (int p = 0; p < 4; ++p) {
        int rlo = row0 + ty*8 + 2*p;
        float klo = usek ? (float)g_ki[rlo]   : 1.f;
        float khi = usek ? (float)g_ki[rlo+1] : 1.f;
#pragma unroll
        for (int j = 0; j < 6; ++j) {
            int col = col0 + tx*6 + j;
            float2 v2 = unpack2(acc2[p][j]);
            float vlo = v2.x + bias[col] * klo;
            float vhi = v2.y + bias[col] * khi;
            if (relu) { vlo = fmaxf(vlo, 0.f); vhi = fmaxf(vhi, 0.f); }
            if (trans) {
                int blo = rlo / NPIX, nlo = rlo % NPIX;
                int bhi = (rlo+1) / NPIX, nhi = (rlo+1) % NPIX;
                C[((size_t)(blo*192 + col))*NPIX + nlo] = vlo;
                C[((size_t)(bhi*192 + col))*NPIX + nhi] = vhi;
            } else {
                C[(size_t)rlo*ldc + col]     = vlo;
                C[(size_t)(rlo+1)*ldc + col] = vhi;
            }
        }
    }
}

// ---------------- launch: fork (mega_prep -> kmlp) onto side stream, hide under dist ----------------
extern "C" void kernel_launch(void* const* d_in, const int* in_sizes, int n_in,
                              void* d_out, int out_size) {
    const float* x      = (const float*)d_in[0];
    const float* kmap_w = (const float*)d_in[1];
    const float* kmap_b = (const float*)d_in[2];
    const float* kfc_w  = (const float*)d_in[3];
    const float* kfc_b  = (const float*)d_in[4];
    const float* kmu_w  = (const float*)d_in[5];
    const float* kmu_b  = (const float*)d_in[6];
    const float* kdec_w = (const float*)d_in[7];
    const float* kdec_b = (const float*)d_in[8];
    const float* ec1_w  = (const float*)d_in[9];
    const float* ec1_b  = (const float*)d_in[10];
    const float* ec2_w  = (const float*)d_in[11];
    const float* ec2_b  = (const float*)d_in[12];
    const float* fc_w   = (const float*)d_in[13];
    const float* fc_b   = (const float*)d_in[14];
    const float* io_w   = (const float*)d_in[15];
    const float* io_b   = (const float*)d_in[16];
    const float* up_w   = (const float*)d_in[17];
    const float* up_b   = (const float*)d_in[18];
    float* out = (float*)d_out;

    // created once on the first (uncaptured) correctness call; reused by capture
    static cudaStream_t s2 = nullptr;
    static cudaEvent_t evFork = nullptr, evJoin = nullptr;
    if (!s2) {
        cudaStreamCreateWithFlags(&s2, cudaStreamNonBlocking);
        cudaEventCreateWithFlags(&evFork, cudaEventDisableTiming);
        cudaEventCreateWithFlags(&evJoin, cudaEventDisableTiming);
    }

    const int dist_smem = (ROWS_B*RFS + CTILE*CSS + ROWS_B*DSS + CTILE) * 4;  // 67840
    cudaFuncSetAttribute(dist_topk5, cudaFuncAttributeMaxDynamicSharedMemorySize, dist_smem);

    // main stream: transpose -> sq
    transpose_kernel<<<dim3(NPIX/32, CH/32, BATCH), dim3(32,32)>>>(x);
    sq_kernel<<<(NODES+255)/256, 256>>>();

    // fork: side stream runs mega_prep -> kmlp while main stream runs dist
    cudaEventRecord(evFork, 0);
    cudaStreamWaitEvent(s2, evFork, 0);
    mega_prep<<<388, 256, 0, s2>>>(kmap_w, kmap_b, kfc_w, kfc_b, kmu_w, kmu_b,
                                   kdec_w, kdec_b, ec1_w, ec2_w,
                                   io_w, io_b, fc_w, fc_b, up_w, up_b);
    kmlp_kernel<<<NODES/128, 128, 0, s2>>>();
    cudaEventRecord(evJoin, s2);

    dist_topk5<<<dim3(NPIX/ROWS_B, BATCH), 128, dist_smem>>>();

    // join: gather needs g_nn (dist, main) + g_ki (kmlp, s2) + Wcat (mega_prep, s2)
    cudaStreamWaitEvent(0, evJoin, 0);

    gather_kernel<<<(NODES*CH+255)/256, 256>>>(0);
    gemm_kernel<<<dim3(NODES/128, 1), 256>>>(0, ec1_b, nullptr);
    gather_kernel<<<(NODES*CH+255)/256, 256>>>(1);
    gemm_kernel<<<dim3(NODES/128, 1), 256>>>(1, ec2_b, nullptr);
    gemm_kernel<<<dim3(NODES/128, 2), 256>>>(2, nullptr, out);
    (void)in_sizes; (void)n_in; (void)out_size;
}

// round 17
// speedup vs baseline: 1.6634x; 1.0297x over previous
#include <cuda_runtime.h>
#include <cstdint>

// Problem constants
#define BATCH 8
#define CH    96
#define NPIX  3136          // 56*56
#define NODES (BATCH*NPIX)  // 25088
#define KNN   9
#define COUT  192

// dist tiling (R6/R14 proven config -- DO NOT TOUCH)
#define ROWS_B 64
#define CTILE  64
#define NTILES (NPIX/CTILE) // 49
#define RFS    98
#define CSS    98
#define DSS    68

typedef unsigned long long u64;

__device__ __forceinline__ void ffma2(u64& d, u64 a, u64 b) {
    asm("fma.rn.f32x2 %0, %1, %2, %3;" : "=l"(d) : "l"(a), "l"(b), "l"(d));
}
__device__ __forceinline__ float2 unpack2(u64 a) {
    float2 r; asm("mov.b64 {%0,%1}, %2;" : "=f"(r.x), "=f"(r.y) : "l"(a)); return r;
}
__device__ __forceinline__ u64 pack2(float lo, float hi) {
    u64 r; asm("mov.b64 %0, {%1,%2};" : "=l"(r) : "f"(lo), "f"(hi)); return r;
}

// ---------------- device scratch (static globals; no allocation) ----------------
__device__ float g_xf[NODES*CH];        // [node, c] node features
__device__ float g_sq[NODES];           // per-node squared norm
__device__ int   g_nn[NODES*KNN];       // global neighbor indices, topk order
__device__ int   g_ki[NODES];           // kept degree per node
__device__ float g_W1c[CH*64];          // folded kmap@kfc
__device__ float g_b1c[64];
__device__ float g_W2c[64*KNN];         // folded kmu@kdec
__device__ float g_b2c[KNN];
__device__ float g_Wcat1[192*96];       // [Wa-Wb ; Wb] of ec1
__device__ float g_Wcat2[192*96];       // of ec2
__device__ float g_Wcat3[192*192];      // [io_w@Up1 ; fc_w@Up2]
__device__ float g_bias3[192];
__device__ float g_Wbig[288*192];       // [W3a ; Wcat2@W3b]
__device__ float g_bvec[192];           // ec2_b @ W3b
__device__ float g_A1[NODES*192];       // conv1 input buffer
__device__ float g_Abig[NODES*288];     // [xf | ki*h1 | sum h1] final input
__device__ float g_h1[NODES*CH];        // conv1 output

// ---------------- transpose x[B,C,H,W] -> xf[node, c] ----------------
__global__ void transpose_kernel(const float* __restrict__ x) {
    __shared__ float t[32][33];
    int b = blockIdx.z, c0 = blockIdx.y * 32, n0 = blockIdx.x * 32;
    int tx = threadIdx.x, ty = threadIdx.y;
    t[ty][tx] = x[((size_t)b*CH + (c0+ty))*NPIX + (n0+tx)];
    __syncthreads();
    g_xf[((size_t)b*NPIX + (n0+ty))*CH + (c0+tx)] = t[tx][ty];
}

// ---------------- per-node squared norm ----------------
__global__ void sq_kernel() {
    int i = blockIdx.x * blockDim.x + threadIdx.x;
    if (i >= NODES) return;
    const float4* p = (const float4*)(g_xf + (size_t)i*CH);
    float a0=0,a1=0,a2=0,a3=0;
#pragma unroll
    for (int c4 = 0; c4 < CH/4; ++c4) {
        float4 v = p[c4];
        a0 = fmaf(v.x, v.x, a0);
        a1 = fmaf(v.y, v.y, a1);
        a2 = fmaf(v.z, v.z, a2);
        a3 = fmaf(v.w, v.w, a3);
    }
    g_sq[i] = (a0+a1)+(a2+a3);
}

// ---------------- fused weight folding (one launch, k1 k-split x4) ----------------
__global__ __launch_bounds__(256) void mega_prep(
    const float* __restrict__ kmap_w, const float* __restrict__ kmap_b,
    const float* __restrict__ kfc_w,  const float* __restrict__ kfc_b,
    const float* __restrict__ kmu_w,  const float* __restrict__ kmu_b,
    const float* __restrict__ kdec_w, const float* __restrict__ kdec_b,
    const float* __restrict__ ec1_w,  const float* __restrict__ ec2_w,
    const float* __restrict__ io_w,   const float* __restrict__ io_b,
    const float* __restrict__ fc_w,   const float* __restrict__ fc_b,
    const float* __restrict__ up_w,   const float* __restrict__ up_b)
{
    int bid = blockIdx.x;
    if (bid < 97) {
        __shared__ float part[4][64];
        int h = threadIdx.x & 63, s = threadIdx.x >> 6;
        const float* a = (bid < 96) ? (kmap_w + bid*500) : kmap_b;
        float acc = 0.f;
        int k0 = s*125;
        for (int k = k0; k < k0+125; ++k) acc = fmaf(a[k], kfc_w[k*64+h], acc);
        part[s][h] = acc;
        __syncthreads();
        if (s == 0) {
            float v = (part[0][h]+part[1][h]) + (part[2][h]+part[3][h]);
            if (bid < 96) g_W1c[bid*64+h] = v;
            else          g_b1c[h] = v + kfc_b[h];
        }
    } else if (bid < 100) {
        int idx = (bid-97)*256 + threadIdx.x;
        if (idx < 64*KNN) {
            int h = idx / KNN, j = idx % KNN;
            float acc = 0.f;
            for (int t = 0; t < 32; ++t) acc = fmaf(kmu_w[h*32+t], kdec_w[t*KNN+j], acc);
            g_W2c[idx] = acc;
        }
        if (idx < KNN) {
            float acc = kdec_b[idx];
            for (int t = 0; t < 32; ++t) acc = fmaf(kmu_b[t], kdec_w[t*KNN+idx], acc);
            g_b2c[idx] = acc;
        }
    } else if (bid < 172) {
        int idx = (bid-100)*256 + threadIdx.x;
        if (idx < 192*96) {
            int k = idx / 96;
            g_Wcat1[idx] = (k < 96) ? (ec1_w[idx] - ec1_w[idx + 96*96]) : ec1_w[idx];
        }
    } else if (bid < 244) {
        int idx = (bid-172)*256 + threadIdx.x;
        if (idx < 192*96) {
            int k = idx / 96;
            g_Wcat2[idx] = (k < 96) ? (ec2_w[idx] - ec2_w[idx + 96*96]) : ec2_w[idx];
        }
    } else {
        int idx = (bid-244)*256 + threadIdx.x;
        if (idx < 192*192) {
            int r = idx / 192, j = idx % 192;
            float acc = 0.f;
            if (r < 96) {
                for (int t = 0; t < 192; ++t) acc = fmaf(io_w[r*192+t], up_w[t*192+j], acc);
            } else {
                int c = r - 96;
                for (int t = 0; t < 192; ++t) acc = fmaf(fc_w[c*192+t], up_w[(192+t)*192+j], acc);
            }
            g_Wcat3[idx] = acc;
        }
        if (idx < 192) {
            float acc = up_b[idx];
            for (int t = 0; t < 192; ++t) acc = fmaf(io_b[t], up_w[t*192+idx], acc);
            for (int t = 0; t < 192; ++t) acc = fmaf(fc_b[t], up_w[(192+t)*192+idx], acc);
            g_bias3[idx] = acc;
        }
    }
}

// ---------------- prep2: fold conv2 into final GEMM (runs after mega_prep on s2) ----------------
// Wbig rows 0..95   = Wcat3 rows 0..95 (W3a, xf part)
// Wbig rows 96..287 = W23 = Wcat2 @ W3b  (W3b = Wcat3 rows 96..191)
// bvec = ec2_b @ W3b
__global__ __launch_bounds__(256) void prep2(const float* __restrict__ ec2_b) {
    int idx = blockIdx.x * 256 + threadIdx.x;
    if (idx < 288*192) {
        int r = idx / 192, j = idx % 192;
        if (r < 96) {
            g_Wbig[idx] = g_Wcat3[r*192 + j];
        } else {
            int k = r - 96;
            float acc = 0.f;
            for (int c = 0; c < 96; ++c)
                acc = fmaf(g_Wcat2[k*96 + c], g_Wcat3[(96+c)*192 + j], acc);
            g_Wbig[idx] = acc;
        }
    }
    if (idx < 192) {
        float acc = 0.f;
        for (int c = 0; c < 96; ++c)
            acc = fmaf(ec2_b[c], g_Wcat3[(96+c)*192 + idx], acc);
        g_bvec[idx] = acc;
    }
}

// ---------------- GEMM-tiled distance + exact top-9 (R6/R14 proven, verbatim) ----------------
__global__ __launch_bounds__(128, 3) void dist_topk5() {
    extern __shared__ float smem[];
    float* Rf  = smem;                       // [64][RFS]
    float* Cs  = Rf + ROWS_B*RFS;            // [64][CSS]
    float* Ds  = Cs + CTILE*CSS;             // [64][DSS]
    float* csq = Ds + ROWS_B*DSS;            // [64]

    int tid = threadIdx.x;
    int b    = blockIdx.y;
    int row0 = blockIdx.x * ROWS_B;
    int grow0 = b * NPIX + row0;
    const float* xb = g_xf + (size_t)b * NPIX * CH;

    for (int idx = tid; idx < ROWS_B*(CH/2); idx += 128) {
        int r = idx / (CH/2), k2 = idx % (CH/2);
        *(float2*)&Rf[r*RFS + k2*2] =
            *(const float2*)(g_xf + (size_t)(grow0 + r)*CH + k2*2);
    }

    int r0 = (tid >> 3) << 2;
    int ct = tid & 7;
    int srow = tid >> 1, sstr = tid & 1;
    float rsq = g_sq[grow0 + srow];

    float d[KNN]; int id[KNN];
#pragma unroll
    for (int j = 0; j < KNN; ++j) { d[j] = 3.4e38f; id[j] = 0x7fffffff; }

    for (int tile = 0; tile < NTILES; ++tile) {
        int col0 = tile * CTILE;
        for (int idx = tid; idx < CTILE*(CH/2); idx += 128) {
            int c = idx / (CH/2), k2 = idx % (CH/2);
            *(float2*)&Cs[c*CSS + k2*2] =
                *(const float2*)(xb + (size_t)(col0 + c)*CH + k2*2);
        }
        if (tid < CTILE) csq[tid] = g_sq[b*NPIX + col0 + tid];
        __syncthreads();

        u64 acc[4][8];
#pragma unroll
        for (int i = 0; i < 4; ++i)
#pragma unroll
            for (int j = 0; j < 8; ++j) acc[i][j] = 0ull;
#pragma unroll 4
        for (int k2 = 0; k2 < CH/2; ++k2) {
            u64 b0 = *(const u64*)&Cs[(ct+ 0)*CSS + 2*k2];
            u64 b1 = *(const u64*)&Cs[(ct+ 8)*CSS + 2*k2];
            u64 b2 = *(const u64*)&Cs[(ct+16)*CSS + 2*k2];
            u64 b3 = *(const u64*)&Cs[(ct+24)*CSS + 2*k2];
            u64 b4 = *(const u64*)&Cs[(ct+32)*CSS + 2*k2];
            u64 b5 = *(const u64*)&Cs[(ct+40)*CSS + 2*k2];
            u64 b6 = *(const u64*)&Cs[(ct+48)*CSS + 2*k2];
            u64 b7 = *(const u64*)&Cs[(ct+56)*CSS + 2*k2];
#pragma unroll
            for (int i = 0; i < 4; ++i) {
                u64 av = *(const u64*)&Rf[(r0+i)*RFS + 2*k2];
                ffma2(acc[i][0], av, b0); ffma2(acc[i][1], av, b1);
                ffma2(acc[i][2], av, b2); ffma2(acc[i][3], av, b3);
                ffma2(acc[i][4], av, b4); ffma2(acc[i][5], av, b5);
                ffma2(acc[i][6], av, b6); ffma2(acc[i][7], av, b7);
            }
        }
#pragma unroll
        for (int i = 0; i < 4; ++i) {
            float* dr = &Ds[(r0+i)*DSS];
#pragma unroll
            for (int j = 0; j < 8; ++j) {
                float2 s = unpack2(acc[i][j]);
                dr[ct + 8*j] = csq[ct + 8*j] - 2.f*(s.x + s.y);
            }
        }
        __syncthreads();

        const float* dsrow = &Ds[srow*DSS + sstr*32];
        int gbase = b*NPIX + col0 + sstr*32;
#pragma unroll
        for (int t = 0; t < 8; ++t) {
            float4 dv = *(const float4*)&dsrow[t*4];
            float dcs[4] = {rsq + dv.x, rsq + dv.y, rsq + dv.z, rsq + dv.w};
#pragma unroll
            for (int u = 0; u < 4; ++u) {
                float dc = dcs[u];
                if (dc < d[KNN-1]) {
                    d[KNN-1] = dc; id[KNN-1] = gbase + t*4 + u;
#pragma unroll
                    for (int j = KNN-1; j > 0; --j) {
                        if (d[j] < d[j-1]) {
                            float td = d[j]; d[j] = d[j-1]; d[j-1] = td;
                            int ti = id[j]; id[j] = id[j-1]; id[j-1] = ti;
                        }
                    }
                }
            }
        }
        __syncthreads();
    }

    float* pd = Cs;
    int*   pi = (int*)Rf;
#pragma unroll
    for (int j = 0; j < KNN; ++j) { pd[tid*KNN + j] = d[j]; pi[tid*KNN + j] = id[j]; }
    __syncthreads();
    if (sstr == 0) {
        const float* dA = &pd[tid*KNN];      const int* iA = &pi[tid*KNN];
        const float* dB = &pd[(tid+1)*KNN];  const int* iB = &pi[(tid+1)*KNN];
        int p = 0, q = 0;
        int* dst = g_nn + (size_t)(grow0 + srow)*KNN;
#pragma unroll
        for (int j = 0; j < KNN; ++j) {
            float da = dA[p], db = dB[q];
            bool takeA = (da < db) || (da == db && iA[p] < iB[q]);
            dst[j] = takeA ? iA[p++] : iB[q++];
        }
    }
}

// ---------------- folded K-predictor MLP + argmax (R14 proven form) ----------------
__global__ __launch_bounds__(128) void kmlp_kernel() {
    __shared__ float sW1[CH*64];
    __shared__ float sW2[64*KNN];
    __shared__ float sb1[64];
    __shared__ float sb2[KNN];
    for (int t = threadIdx.x; t < CH*64; t += 128) sW1[t] = g_W1c[t];
    for (int t = threadIdx.x; t < 64*KNN; t += 128) sW2[t] = g_W2c[t];
    if (threadIdx.x < 64) sb1[threadIdx.x] = g_b1c[threadIdx.x];
    if (threadIdx.x < KNN) sb2[threadIdx.x] = g_b2c[threadIdx.x];
    __syncthreads();

    int i = blockIdx.x * 128 + threadIdx.x;
    float xr[CH];
#pragma unroll
    for (int c4 = 0; c4 < CH/4; ++c4) {
        float4 v = *(const float4*)(g_xf + (size_t)i*CH + c4*4);
        xr[c4*4+0]=v.x; xr[c4*4+1]=v.y; xr[c4*4+2]=v.z; xr[c4*4+3]=v.w;
    }
    float lg[KNN];
#pragma unroll
    for (int j = 0; j < KNN; ++j) lg[j] = sb2[j];

    for (int h = 0; h < 64; ++h) {
        float a0=0,a1=0,a2=0,a3=0;
#pragma unroll
        for (int c = 0; c < CH; c += 4) {
            a0 = fmaf(xr[c+0], sW1[(c+0)*64+h], a0);
            a1 = fmaf(xr[c+1], sW1[(c+1)*64+h], a1);
            a2 = fmaf(xr[c+2], sW1[(c+2)*64+h], a2);
            a3 = fmaf(xr[c+3], sW1[(c+3)*64+h], a3);
        }
        float hv = fmaxf((a0+a1)+(a2+a3) + sb1[h], 0.f);
#pragma unroll
        for (int j = 0; j < KNN; ++j) lg[j] = fmaf(hv, sW2[h*KNN+j], lg[j]);
    }
    float best = lg[0]; int bi = 0;
#pragma unroll
    for (int j = 1; j < KNN; ++j) if (lg[j] > best) { best = lg[j]; bi = j; }
    g_ki[i] = bi;
}

// ---------------- gathers: MLP-unrolled (all 9 loads in flight) ----------------
// mode 0: A1 = [ki*xf | sum_{e<ki} xf[nn]]          (stride 192)
// mode 1: Abig = [xf | ki*h1 | sum_{e<ki} h1[nn]]   (stride 288)
__global__ void gather_kernel(int mode) {
    const float* feat = mode ? g_h1 : g_xf;
    int idx = blockIdx.x * blockDim.x + threadIdx.x;
    if (idx >= NODES*CH) return;
    int i = idx / CH, c = idx % CH;
    int k = g_ki[i];
    const int* nrow = g_nn + (size_t)i*KNN;
    int ni[KNN];
#pragma unroll
    for (int e = 0; e < KNN; ++e) ni[e] = nrow[e];
    float v[KNN];
#pragma unroll
    for (int e = 0; e < KNN; ++e) v[e] = feat[(size_t)ni[e]*CH + c];
    float s = 0.f;
#pragma unroll
    for (int e = 0; e < KNN; ++e) s += (e < k) ? v[e] : 0.f;
    float self = feat[(size_t)i*CH + c];
    if (mode) {
        g_Abig[(size_t)i*288 + c]       = g_xf[(size_t)i*CH + c];
        g_Abig[(size_t)i*288 + 96 + c]  = (float)k * self;
        g_Abig[(size_t)i*288 + 192 + c] = s;
    } else {
        g_A1[(size_t)i*192 + c]      = (float)k * self;
        g_A1[(size_t)i*192 + 96 + c] = s;
    }
}

// ---------------- GEMM (generic): [25088, K] @ [K, 96-col tile], f32x2-packed ----------------
// mode 0: h1 = relu(A1@Wcat1 + ki*ec1_b)     A=g_A1, lda=192, K=192, C=g_h1 (ldc 96)
// mode 2: out = relu(Abig@Wbig + bias3 + ki*bvec), transposed store [B,192,N]
__global__ __launch_bounds__(256) void gemm_kernel(int mode, const float* __restrict__ bias_in,
                                                   float* __restrict__ dout) {
    const float* A; const float* W; float* C;
    int lda, KD, ldw, ldc, relu, trans;
    if (mode == 0) { A=g_A1;   W=g_Wcat1; C=g_h1; lda=192; KD=192; ldw=96;  ldc=96;  relu=1; trans=0; }
    else           { A=g_Abig; W=g_Wbig;  C=dout; lda=288; KD=288; ldw=192; ldc=192; relu=1; trans=1; }

    __shared__ float As[16][128];
    __shared__ float Bs[16][96];
    int tid = threadIdx.x;
    int tx = tid % 16, ty = tid / 16;
    int row0 = blockIdx.x * 128;
    int col0 = blockIdx.y * 96;

    u64 acc2[4][6];
#pragma unroll
    for (int p = 0; p < 4; ++p)
#pragma unroll
        for (int j = 0; j < 6; ++j) acc2[p][j] = 0ull;

    for (int kk = 0; kk < KD; kk += 16) {
#pragma unroll
        for (int l = 0; l < 2; ++l) {
            int idx = tid + l*256;
            int r = idx >> 2, k4 = idx & 3;
            float4 v = *(const float4*)(A + (size_t)(row0 + r)*lda + kk + k4*4);
            As[k4*4+0][r] = v.x; As[k4*4+1][r] = v.y; As[k4*4+2][r] = v.z; As[k4*4+3][r] = v.w;
        }
#pragma unroll
        for (int l = 0; l < 2; ++l) {
            int idx = tid + l*256;
            if (idx < 384) {
                int k = idx / 24, c4 = idx % 24;
                float4 v = *(const float4*)(W + (size_t)(kk+k)*ldw + col0 + c4*4);
                *(float4*)&Bs[k][c4*4] = v;
            }
        }
        __syncthreads();
#pragma unroll
        for (int k = 0; k < 16; ++k) {
            ulonglong2 a01 = *(const ulonglong2*)&As[k][ty*8];
            ulonglong2 a23 = *(const ulonglong2*)&As[k][ty*8+4];
            u64 ap[4] = {a01.x, a01.y, a23.x, a23.y};
            float2 bv0 = *(const float2*)&Bs[k][tx*6];
            float2 bv1 = *(const float2*)&Bs[k][tx*6+2];
            float2 bv2 = *(const float2*)&Bs[k][tx*6+4];
            u64 bp[6];
            bp[0] = pack2(bv0.x, bv0.x); bp[1] = pack2(bv0.y, bv0.y);
            bp[2] = pack2(bv1.x, bv1.x); bp[3] = pack2(bv1.y, bv1.y);
            bp[4] = pack2(bv2.x, bv2.x); bp[5] = pack2(bv2.y, bv2.y);
#pragma unroll
            for (int p = 0; p < 4; ++p)
#pragma unroll
                for (int j = 0; j < 6; ++j) ffma2(acc2[p][j], ap[p], bp[j]);
        }
        __syncthreads();
    }

#pragma unroll
    for (int p = 0; p < 4; ++p) {
        int rlo = row0 + ty*8 + 2*p;
        float klo = (float)g_ki[rlo];
        float khi = (float)g_ki[rlo+1];
#pragma unroll
        for (int j = 0; j < 6; ++j) {
            int col = col0 + tx*6 + j;
            float2 v2 = unpack2(acc2[p][j]);
            float vlo, vhi;
            if (mode == 0) {
                vlo = v2.x + bias_in[col] * klo;
                vhi = v2.y + bias_in[col] * khi;
            } else {
                vlo = v2.x + g_bias3[col] + g_bvec[col] * klo;
                vhi = v2.y + g_bias3[col] + g_bvec[col] * khi;
            }
            if (relu) { vlo = fmaxf(vlo, 0.f); vhi = fmaxf(vhi, 0.f); }
            if (trans) {
                int blo = rlo / NPIX, nlo = rlo % NPIX;
                int bhi = (rlo+1) / NPIX, nhi = (rlo+1) % NPIX;
                C[((size_t)(blo*192 + col))*NPIX + nlo] = vlo;
                C[((size_t)(bhi*192 + col))*NPIX + nhi] = vhi;
            } else {
                C[(size_t)rlo*ldc + col]     = vlo;
                C[(size_t)(rlo+1)*ldc + col] = vhi;
            }
        }
    }
}

// ---------------- launch: side-stream prep hidden under dist ----------------
extern "C" void kernel_launch(void* const* d_in, const int* in_sizes, int n_in,
                              void* d_out, int out_size) {
    const float* x      = (const float*)d_in[0];
    const float* kmap_w = (const float*)d_in[1];
    const float* kmap_b = (const float*)d_in[2];
    const float* kfc_w  = (const float*)d_in[3];
    const float* kfc_b  = (const float*)d_in[4];
    const float* kmu_w  = (const float*)d_in[5];
    const float* kmu_b  = (const float*)d_in[6];
    const float* kdec_w = (const float*)d_in[7];
    const float* kdec_b = (const float*)d_in[8];
    const float* ec1_w  = (const float*)d_in[9];
    const float* ec1_b  = (const float*)d_in[10];
    const float* ec2_w  = (const float*)d_in[11];
    const float* ec2_b  = (const float*)d_in[12];
    const float* fc_w   = (const float*)d_in[13];
    const float* fc_b   = (const float*)d_in[14];
    const float* io_w   = (const float*)d_in[15];
    const float* io_b   = (const float*)d_in[16];
    const float* up_w   = (const float*)d_in[17];
    const float* up_b   = (const float*)d_in[18];
    float* out = (float*)d_out;

    static cudaStream_t s2 = nullptr;
    static cudaEvent_t evFork = nullptr, evJoin = nullptr;
    if (!s2) {
        cudaStreamCreateWithFlags(&s2, cudaStreamNonBlocking);
        cudaEventCreateWithFlags(&evFork, cudaEventDisableTiming);
        cudaEventCreateWithFlags(&evJoin, cudaEventDisableTiming);
    }

    const int dist_smem = (ROWS_B*RFS + CTILE*CSS + ROWS_B*DSS + CTILE) * 4;  // 67840
    cudaFuncSetAttribute(dist_topk5, cudaFuncAttributeMaxDynamicSharedMemorySize, dist_smem);

    // main stream: transpose -> sq
    transpose_kernel<<<dim3(NPIX/32, CH/32, BATCH), dim3(32,32)>>>(x);
    sq_kernel<<<(NODES+255)/256, 256>>>();

    // fork: side stream runs mega_prep -> prep2 -> kmlp while main stream runs dist
    cudaEventRecord(evFork, 0);
    cudaStreamWaitEvent(s2, evFork, 0);
    mega_prep<<<388, 256, 0, s2>>>(kmap_w, kmap_b, kfc_w, kfc_b, kmu_w, kmu_b,
                                   kdec_w, kdec_b, ec1_w, ec2_w,
                                   io_w, io_b, fc_w, fc_b, up_w, up_b);
    prep2<<<(288*192+255)/256, 256, 0, s2>>>(ec2_b);
    kmlp_kernel<<<NODES/128, 128, 0, s2>>>();
    cudaEventRecord(evJoin, s2);

    dist_topk5<<<dim3(NPIX/ROWS_B, BATCH), 128, dist_smem>>>();

    // join: epilogue needs g_nn (dist) + g_ki/Wcat/Wbig (s2)
    cudaStreamWaitEvent(0, evJoin, 0);

    gather_kernel<<<(NODES*CH+255)/256, 256>>>(0);
    gemm_kernel<<<dim3(NODES/128, 1), 256>>>(0, ec1_b, nullptr);
    gather_kernel<<<(NODES*CH+255)/256, 256>>>(1);
    gemm_kernel<<<dim3(NODES/128, 2), 256>>>(2, nullptr, out);
    (void)in_sizes; (void)n_in; (void)out_size;
}